// round 1
// baseline (speedup 1.0000x reference)
#include <cuda_runtime.h>
#include <cstdint>

#define GRID    148
#define NTHREADS 512
#define BB   256
#define TT   64
#define NIN  128
#define HH   512
#define KTOT 640          // HH + NIN
#define NBACT 128         // blocks active in phase B (128 * 4 cols = 512)

typedef unsigned long long ull;

// ---------------- global scratch (allowed: __device__ globals) ----------------
__device__ float g_z2[BB * NIN * TT];      // [b][n][s]  loop-invariant attention term
__device__ float g_Xt[2][KTOT * BB];       // [buf][k][b]: rows 0..511 = h, 512..639 = wx
__device__ float g_Ct[HH * BB];            // [k][b] cell state (for phase A reads)
__device__ unsigned g_cnt = 0;
__device__ unsigned g_gen = 0;

// ---------------- shared layouts ----------------
struct SmemMain {
    float2 ws2[KTOT * 16];      // duplicated (w,w) weight slice, 80 KB
    float  hss[2][1024];        // staged [h|c] for this block's 1-2 batches
    float  z1s[2][64];
    float  epart[2][2][128];    // [sgrp][half][n]
    float  wa3s[64];
    float  ba1s[64];
    float  redm[8];
    float  reds[8];
    float  ba3v;
};
struct SmemPre {                // overlays ws2 region during z2 precompute
    float dxs[TT * NIN];        // 32 KB
    float wa2s[TT * TT];        // 16 KB
};

// ---------------- helpers ----------------
__device__ __forceinline__ ull ffma2(ull a, ull b, ull c) {
    ull d;
    asm("fma.rn.f32x2 %0, %1, %2, %3;" : "=l"(d) : "l"(a), "l"(b), "l"(c));
    return d;
}
__device__ __forceinline__ float f2lo(ull a) { return __uint_as_float((unsigned)(a & 0xffffffffull)); }
__device__ __forceinline__ float f2hi(ull a) { return __uint_as_float((unsigned)(a >> 32)); }
__device__ __forceinline__ float tanha(float x) {
    float y; asm("tanh.approx.f32 %0, %1;" : "=f"(y) : "f"(x)); return y;
}
__device__ __forceinline__ float sigm(float x) { return 0.5f * tanha(0.5f * x) + 0.5f; }

__device__ __forceinline__ void grid_sync() {
    __threadfence();
    __syncthreads();
    if (threadIdx.x == 0) {
        unsigned gen = *((volatile unsigned*)&g_gen);
        if (atomicAdd(&g_cnt, 1u) == GRID - 1) {
            g_cnt = 0;
            __threadfence();
            atomicAdd(&g_gen, 1u);
        } else {
            while (*((volatile unsigned*)&g_gen) == gen) { __nanosleep(32); }
        }
    }
    __syncthreads();
}

// ---------------- the persistent kernel ----------------
__global__ void __launch_bounds__(NTHREADS, 2)
attn_lstm_kernel(const float* __restrict__ dx,   const float* __restrict__ W_a1,
                 const float* __restrict__ b_a1, const float* __restrict__ W_a2,
                 const float* __restrict__ b_a2, const float* __restrict__ W_a3,
                 const float* __restrict__ b_a3, const float* __restrict__ W_ih,
                 const float* __restrict__ W_hh, const float* __restrict__ b_ih,
                 const float* __restrict__ b_hh, float* __restrict__ out)
{
    extern __shared__ char smem_raw[];
    SmemMain* sm = (SmemMain*)smem_raw;
    SmemPre*  sp = (SmemPre*)smem_raw;

    const int tid  = threadIdx.x;
    const int bid  = blockIdx.x;
    const int lane = tid & 31;
    const int wid  = tid >> 5;

    // ---- init: zero h(-1) buffer and cell-state mirror (re-done every launch)
    for (int idx = bid * NTHREADS + tid; idx < HH * BB; idx += GRID * NTHREADS) {
        g_Xt[0][idx] = 0.f;
        g_Ct[idx]    = 0.f;
    }

    const int nb = (bid < BB - GRID) ? 2 : 1;   // 108 blocks own 2 batches

    // ---- z2 precompute: z2[b][n][s] = sum_t dx[b][t][n]*W_a2[s][t] + b_a2[s]
    for (int idx = tid; idx < TT * TT; idx += NTHREADS) sp->wa2s[idx] = W_a2[idx];
    for (int bh = 0; bh < nb; bh++) {
        const int b = bid + bh * GRID;
        __syncthreads();
        for (int idx = tid; idx < TT * NIN; idx += NTHREADS)
            sp->dxs[idx] = dx[b * TT * NIN + idx];
        __syncthreads();
        // warp w: n = (w&3)*32+lane, s-range = (w>>2)*16 .. +15
        const int n  = ((wid & 3) << 5) + lane;
        const int s0 = (wid >> 2) << 4;
        float acc[16];
        #pragma unroll
        for (int j = 0; j < 16; j++) acc[j] = b_a2[s0 + j];
        for (int t = 0; t < TT; t++) {
            const float xv = sp->dxs[t * NIN + n];
            #pragma unroll
            for (int j = 0; j < 16; j++) acc[j] += xv * sp->wa2s[(s0 + j) * TT + t];
        }
        float* zp = &g_z2[(b * NIN + n) * TT + s0];
        #pragma unroll
        for (int j = 0; j < 16; j += 4)
            *(float4*)(zp + j) = make_float4(acc[j], acc[j+1], acc[j+2], acc[j+3]);
    }
    __syncthreads();

    // ---- small constants
    if (tid < 64) { sm->wa3s[tid] = W_a3[tid]; sm->ba1s[tid] = b_a1[tid]; }
    if (tid == 64) sm->ba3v = b_a3[0];

    // ---- weight-stationary slice for phase B (overwrites precompute scratch)
    int c0 = 0, group = 0, b0 = 0;
    float bs0 = 0.f, bs1 = 0.f, bs2 = 0.f, bs3 = 0.f;
    float2 creg = make_float2(0.f, 0.f);
    if (bid < NBACT) {
        c0    = bid * 4;
        group = tid >> 7;            // 0..3 -> this thread's h-column
        b0    = (tid & 127) * 2;     // 2 batches per thread (f32x2)
        for (int idx = tid; idx < KTOT * 16; idx += NTHREADS) {
            const int k = idx >> 4, r = idx & 15;
            const int col = c0 + (r >> 2), gate = r & 3;
            const int row = gate * HH + col;
            const float w = (k < HH) ? W_hh[row * HH + k] : W_ih[row * NIN + (k - HH)];
            sm->ws2[idx] = make_float2(w, w);
        }
        const int col = c0 + group;
        bs0 = b_ih[0 * HH + col] + b_hh[0 * HH + col];
        bs1 = b_ih[1 * HH + col] + b_hh[1 * HH + col];
        bs2 = b_ih[2 * HH + col] + b_hh[2 * HH + col];
        bs3 = b_ih[3 * HH + col] + b_hh[3 * HH + col];
    }
    grid_sync();   // init + z2 visible everywhere

    // ================= main recurrence =================
    for (int t = 0; t < TT; t++) {
        const int r = t & 1;
        float* XtR = g_Xt[r];        // holds h(t-1) rows 0..511; receives wx(t)
        float* XtW = g_Xt[r ^ 1];    // receives h(t)

        // ===== Phase A: attention + softmax -> wx =====
        for (int idx = tid; idx < 2048; idx += NTHREADS) {
            const int bh = idx >> 10;
            if (bh < nb) {
                const int kk = idx & 1023;
                const int b  = bid + bh * GRID;
                sm->hss[bh][kk] = (kk < HH) ? XtR[kk * BB + b] : g_Ct[(kk - HH) * BB + b];
            }
        }
        __syncthreads();
        {   // z1[s] = [h|c] . W_a1[s]  (warp per 8 s-values, per batch-half)
            const int bh = wid >> 3;
            if (bh < nb) {
                const int s0 = (wid & 7) << 3;
                const float* hp = sm->hss[bh];
                #pragma unroll
                for (int j = 0; j < 8; j++) {
                    const int s = s0 + j;
                    const float* wr = &W_a1[s * 1024];
                    float a = 0.f;
                    #pragma unroll 8
                    for (int k = lane; k < 1024; k += 32) a += hp[k] * wr[k];
                    #pragma unroll
                    for (int off = 16; off; off >>= 1) a += __shfl_xor_sync(0xffffffffu, a, off);
                    if (lane == 0) sm->z1s[bh][s] = a + sm->ba1s[s];
                }
            }
        }
        __syncthreads();
        {   // e partials: tanh(z1[s]+z2[n][s])*W_a3[s], s split over two thread halves
            const int n = tid & 127, half = (tid >> 7) & 1, sgrp = tid >> 8;
            if (half < nb) {
                const int b = bid + half * GRID;
                const float* zp  = &g_z2[(b * NIN + n) * TT + sgrp * 32];
                const float* z1p = &sm->z1s[half][sgrp * 32];
                const float* w3p = &sm->wa3s[sgrp * 32];
                float acc = 0.f;
                #pragma unroll
                for (int j = 0; j < 32; j += 4) {
                    const float4 z = *(const float4*)(zp + j);
                    acc += tanha(z1p[j + 0] + z.x) * w3p[j + 0];
                    acc += tanha(z1p[j + 1] + z.y) * w3p[j + 1];
                    acc += tanha(z1p[j + 2] + z.z) * w3p[j + 2];
                    acc += tanha(z1p[j + 3] + z.w) * w3p[j + 3];
                }
                sm->epart[sgrp][half][n] = acc;
            }
        }
        __syncthreads();
        {   // softmax over n (128), wx = w * x_t
            const int n = tid & 127, half = tid >> 7;
            const bool act = (tid < 256) && (half < nb);
            float e = 0.f, xv = 0.f, p = 0.f;
            const int b = bid + half * GRID;
            if (act) {
                e  = sm->epart[0][half][n] + sm->epart[1][half][n] + sm->ba3v;
                xv = dx[(b * TT + t) * NIN + n];
                float m = e;
                #pragma unroll
                for (int off = 16; off; off >>= 1) m = fmaxf(m, __shfl_xor_sync(0xffffffffu, m, off));
                if (lane == 0) sm->redm[wid] = m;
            }
            __syncthreads();
            if (act) {
                const int wb = half * 4;
                const float m4 = fmaxf(fmaxf(sm->redm[wb], sm->redm[wb + 1]),
                                       fmaxf(sm->redm[wb + 2], sm->redm[wb + 3]));
                p = __expf(e - m4);
                float s = p;
                #pragma unroll
                for (int off = 16; off; off >>= 1) s += __shfl_xor_sync(0xffffffffu, s, off);
                if (lane == 0) sm->reds[wid] = s;
            }
            __syncthreads();
            if (act) {
                const int wb = half * 4;
                const float tot = sm->reds[wb] + sm->reds[wb + 1] + sm->reds[wb + 2] + sm->reds[wb + 3];
                XtR[(HH + n) * BB + b] = (p / tot) * xv;
            }
        }
        grid_sync();   // wx visible

        // ===== Phase B: gates GEMM (f32x2) + LSTM pointwise =====
        if (bid < NBACT) {
            ull a0 = 0ull, a1 = 0ull, a2 = 0ull, a3 = 0ull;
            const ulonglong2* wsv = (const ulonglong2*)sm->ws2;
            const float* xb = XtR + b0;
            const int woff = group * 2;
            #pragma unroll 4
            for (int k = 0; k < KTOT; k++) {
                const ull x = *(const ull*)(xb + k * BB);
                const ulonglong2 wA = wsv[k * 8 + woff];
                const ulonglong2 wB = wsv[k * 8 + woff + 1];
                a0 = ffma2(x, wA.x, a0);
                a1 = ffma2(x, wA.y, a1);
                a2 = ffma2(x, wB.x, a2);
                a3 = ffma2(x, wB.y, a3);
            }
            const int col = c0 + group;
            const float i0 = f2lo(a0) + bs0, ff0 = f2lo(a1) + bs1;
            const float gg0 = f2lo(a2) + bs2, o0 = f2lo(a3) + bs3;
            const float i1 = f2hi(a0) + bs0, ff1 = f2hi(a1) + bs1;
            const float gg1 = f2hi(a2) + bs2, o1 = f2hi(a3) + bs3;
            const float cn0 = sigm(ff0) * creg.x + sigm(i0) * tanha(gg0);
            const float cn1 = sigm(ff1) * creg.y + sigm(i1) * tanha(gg1);
            const float hn0 = sigm(o0) * tanha(cn0);
            const float hn1 = sigm(o1) * tanha(cn1);
            creg = make_float2(cn0, cn1);
            *(float2*)&g_Ct[col * BB + b0] = creg;
            *(float2*)&XtW[col * BB + b0] = make_float2(hn0, hn1);
            out[(b0 * TT + t) * HH + col]       = hn0;
            out[((b0 + 1) * TT + t) * HH + col] = hn1;
        }
        grid_sync();   // h(t), c(t) visible
    }
}

// ---------------- launch ----------------
extern "C" void kernel_launch(void* const* d_in, const int* in_sizes, int n_in,
                              void* d_out, int out_size)
{
    const float* dx   = (const float*)d_in[0];
    const float* W_a1 = (const float*)d_in[1];
    const float* b_a1 = (const float*)d_in[2];
    const float* W_a2 = (const float*)d_in[3];
    const float* b_a2 = (const float*)d_in[4];
    const float* W_a3 = (const float*)d_in[5];
    const float* b_a3 = (const float*)d_in[6];
    const float* W_ih = (const float*)d_in[7];
    const float* W_hh = (const float*)d_in[8];
    const float* b_ih = (const float*)d_in[9];
    const float* b_hh = (const float*)d_in[10];
    float* out = (float*)d_out;

    const size_t smem = sizeof(SmemMain);
    cudaFuncSetAttribute(attn_lstm_kernel,
                         cudaFuncAttributeMaxDynamicSharedMemorySize, (int)smem);
    attn_lstm_kernel<<<GRID, NTHREADS, smem>>>(dx, W_a1, b_a1, W_a2, b_a2, W_a3,
                                               b_a3, W_ih, W_hh, b_ih, b_hh, out);
}

// round 2
// speedup vs baseline: 1.1591x; 1.1591x over previous
#include <cuda_runtime.h>
#include <cstdint>

#define GRID     128
#define NTHREADS 256
#define BB   256
#define TT   64
#define NIN  128
#define HH   512
#define KTOT 640          // HH + NIN
#define KSPLIT 4
#define KCHUNK (KTOT / KSPLIT)   // 160

typedef unsigned long long ull;

// ---------------- global scratch ----------------
__device__ __align__(16) float g_z2[BB * TT * NIN];   // [b][s][n]
__device__ __align__(16) float g_Xt[2][KTOT * BB];    // [buf][k][b]: 0..511 h, 512..639 wx
__device__ __align__(16) float g_Ct[HH * BB];         // [k][b]
__device__ unsigned g_cnt = 0;
__device__ unsigned g_gen = 0;

// ---------------- shared ----------------
struct SmemMain {
    ull ws[KTOT * 16];                       // 80KB  [k][o] duplicated (w,w)
    union {
        ull red[3 * 64 * 33];                // ~50.7KB padded reduction buffer
        struct { float dxs[TT * NIN]; float wa2s[TT * TT]; } pre;  // 48KB
    } u;
    float hss[2][1024];                      // 8KB staged [h|c]
    float z1s[2][TT];
    float wa3s[TT];
    float ba1s[TT];
    float redm[8];
    float reds[8];
    float ba3v;
};

// ---------------- helpers ----------------
__device__ __forceinline__ ull ffma2(ull a, ull b, ull c) {
    ull d; asm("fma.rn.f32x2 %0, %1, %2, %3;" : "=l"(d) : "l"(a), "l"(b), "l"(c)); return d;
}
__device__ __forceinline__ ull addf2(ull a, ull b) {
    ull d; asm("add.rn.f32x2 %0, %1, %2;" : "=l"(d) : "l"(a), "l"(b)); return d;
}
__device__ __forceinline__ float f2lo(ull a) { return __uint_as_float((unsigned)(a & 0xffffffffull)); }
__device__ __forceinline__ float f2hi(ull a) { return __uint_as_float((unsigned)(a >> 32)); }
__device__ __forceinline__ ull dupf(float w) {
    unsigned b = __float_as_uint(w); return ((ull)b << 32) | (ull)b;
}
__device__ __forceinline__ float tanha(float x) {
    float y; asm("tanh.approx.f32 %0, %1;" : "=f"(y) : "f"(x)); return y;
}
__device__ __forceinline__ float sigm(float x) { return 0.5f * tanha(0.5f * x) + 0.5f; }
__device__ __forceinline__ void ldcg2(ull& a, ull& b, const float* p) {
    asm volatile("ld.global.cg.v2.u64 {%0,%1}, [%2];" : "=l"(a), "=l"(b) : "l"(p));
}
__device__ __forceinline__ float ldcgf(const float* p) {
    float v; asm volatile("ld.global.cg.f32 %0, [%1];" : "=f"(v) : "l"(p)); return v;
}

__device__ __forceinline__ void grid_sync() {
    __threadfence();
    __syncthreads();
    if (threadIdx.x == 0) {
        unsigned gen = *((volatile unsigned*)&g_gen);
        if (atomicAdd(&g_cnt, 1u) == GRID - 1) {
            g_cnt = 0;
            __threadfence();
            atomicAdd(&g_gen, 1u);
        } else {
            while (*((volatile unsigned*)&g_gen) == gen) { __nanosleep(32); }
        }
    }
    __syncthreads();
}

// ---------------- kernel ----------------
__global__ void __launch_bounds__(NTHREADS, 1)
attn_lstm_kernel(const float* __restrict__ dx,   const float* __restrict__ W_a1,
                 const float* __restrict__ b_a1, const float* __restrict__ W_a2,
                 const float* __restrict__ b_a2, const float* __restrict__ W_a3,
                 const float* __restrict__ b_a3, const float* __restrict__ W_ih,
                 const float* __restrict__ W_hh, const float* __restrict__ b_ih,
                 const float* __restrict__ b_hh, float* __restrict__ out)
{
    extern __shared__ char smem_raw[];
    SmemMain* sm = (SmemMain*)smem_raw;

    const int tid  = threadIdx.x;
    const int bid  = blockIdx.x;
    const int lane = tid & 31;
    const int wid  = tid >> 5;

    // ---- init: zero h(-1) buffer and cell state
    for (int idx = bid * NTHREADS + tid; idx < KTOT * BB; idx += GRID * NTHREADS)
        g_Xt[0][idx] = 0.f;
    for (int idx = bid * NTHREADS + tid; idx < HH * BB; idx += GRID * NTHREADS)
        g_Ct[idx] = 0.f;

    // ---- weight-stationary slice: 4 cols (16 outputs), o = col_local*4 + gate
    const int c0 = bid * 4;
    for (int idx = tid; idx < KTOT * 16; idx += NTHREADS) {
        const int k = idx >> 4, o = idx & 15;
        const int col = c0 + (o >> 2), gate = o & 3;
        const int row = gate * HH + col;
        const float w = (k < HH) ? W_hh[row * HH + k] : W_ih[row * NIN + (k - HH)];
        sm->ws[idx] = dupf(w);
    }

    // ---- z2 precompute: z2[b][s][n] = sum_t dx[b][t][n]*W_a2[s][t] + b_a2[s]
    for (int idx = tid; idx < TT * TT; idx += NTHREADS) sm->u.pre.wa2s[idx] = W_a2[idx];
    for (int bh = 0; bh < 2; bh++) {
        const int b = bid + bh * GRID;
        __syncthreads();
        for (int idx = tid; idx < TT * NIN; idx += NTHREADS)
            sm->u.pre.dxs[idx] = dx[b * TT * NIN + idx];
        __syncthreads();
        // warp w: q = w>>2 -> s-range q*32..+31 ; n = (w&3)*32 + lane
        const int q  = wid >> 2;
        const int n  = ((wid & 3) << 5) + lane;
        const int s0 = q << 5;
        float acc[32];
        #pragma unroll
        for (int j = 0; j < 32; j++) acc[j] = b_a2[s0 + j];
        for (int t = 0; t < TT; t++) {
            const float xv = sm->u.pre.dxs[t * NIN + n];
            #pragma unroll
            for (int j = 0; j < 32; j++) acc[j] += xv * sm->u.pre.wa2s[(s0 + j) * TT + t];
        }
        #pragma unroll
        for (int j = 0; j < 32; j++)
            g_z2[(b * TT + s0 + j) * NIN + n] = acc[j];
    }
    __syncthreads();

    // ---- small constants
    if (tid < TT) { sm->wa3s[tid] = W_a3[tid]; sm->ba1s[tid] = b_a1[tid]; }
    if (tid == 64) sm->ba3v = b_a3[0];

    // ---- phase-B thread identity
    const int ks = tid >> 6;          // 0..3 k-split
    const int bt = tid & 63;          // batch-thread
    const int b0 = bt * 4;            // 4 batches per thread
    const int kbase = ks * KCHUNK;

    // biases + persistent cell state (used by ks==0 threads only)
    float biasv[16], creg[16];
    #pragma unroll
    for (int o = 0; o < 16; o++) {
        const int col = c0 + (o >> 2), gate = o & 3;
        biasv[o] = b_ih[gate * HH + col] + b_hh[gate * HH + col];
        creg[o] = 0.f;
    }

    grid_sync();   // init + z2 visible

    // ================= main recurrence =================
    for (int t = 0; t < TT; t++) {
        const int r = t & 1;
        float* XtR = g_Xt[r];
        float* XtW = g_Xt[r ^ 1];
        const int bA0 = bid;            // this block's two phase-A batches
        const int bA1 = bid + GRID;

        // ===== Phase A =====
        // stage [h|c] for 2 batches (cross-block data -> .cg)
        for (int idx = tid; idx < 2048; idx += NTHREADS) {
            const int bh = idx >> 10, kk = idx & 1023;
            const int b = bid + bh * GRID;
            sm->hss[bh][kk] = (kk < HH) ? ldcgf(&XtR[kk * BB + b])
                                        : ldcgf(&g_Ct[(kk - HH) * BB + b]);
        }
        __syncthreads();
        {   // z1: warp handles s = wid*8..+7 for BOTH batches (W_a1 row read once)
            const int s0 = wid << 3;
            #pragma unroll
            for (int j = 0; j < 8; j++) {
                const int s = s0 + j;
                const float* wr = &W_a1[s * 1024];
                float a0 = 0.f, a1 = 0.f;
                #pragma unroll 8
                for (int k = lane; k < 1024; k += 32) {
                    const float w = wr[k];
                    a0 += w * sm->hss[0][k];
                    a1 += w * sm->hss[1][k];
                }
                #pragma unroll
                for (int off = 16; off; off >>= 1) {
                    a0 += __shfl_xor_sync(0xffffffffu, a0, off);
                    a1 += __shfl_xor_sync(0xffffffffu, a1, off);
                }
                if (lane == 0) {
                    sm->z1s[0][s] = a0 + sm->ba1s[s];
                    sm->z1s[1][s] = a1 + sm->ba1s[s];
                }
            }
        }
        __syncthreads();
        {   // e + softmax + wx, thread = (bh = tid>>7, n = tid&127)
            const int bh = tid >> 7, n = tid & 127;
            const int b = bid + bh * GRID;
            const float* zp = &g_z2[(b * TT) * NIN + n];
            const float* z1p = sm->z1s[bh];
            float e = sm->ba3v;
            #pragma unroll 8
            for (int s = 0; s < TT; s++)
                e += tanha(z1p[s] + zp[s * NIN]) * sm->wa3s[s];
            const float xv = dx[(b * TT + t) * NIN + n];
            float m = e;
            #pragma unroll
            for (int off = 16; off; off >>= 1) m = fmaxf(m, __shfl_xor_sync(0xffffffffu, m, off));
            if (lane == 0) sm->redm[wid] = m;
            __syncthreads();
            const int wb = bh * 4;
            const float m4 = fmaxf(fmaxf(sm->redm[wb], sm->redm[wb + 1]),
                                   fmaxf(sm->redm[wb + 2], sm->redm[wb + 3]));
            const float p = __expf(e - m4);
            float ssum = p;
            #pragma unroll
            for (int off = 16; off; off >>= 1) ssum += __shfl_xor_sync(0xffffffffu, ssum, off);
            if (lane == 0) sm->reds[wid] = ssum;
            __syncthreads();
            const float tot = sm->reds[wb] + sm->reds[wb + 1] + sm->reds[wb + 2] + sm->reds[wb + 3];
            XtR[(HH + n) * BB + b] = (p / tot) * xv;
        }
        grid_sync();   // wx visible

        // ===== Phase B: gates GEMM, 32 FFMA2 per thread per k =====
        ull acc[32];
        #pragma unroll
        for (int i = 0; i < 32; i++) acc[i] = 0ull;
        {
            const float* xp = XtR + b0;
            const ulonglong2* wsv = (const ulonglong2*)sm->ws;
            ull xc0, xc1, xn0, xn1;
            ldcg2(xc0, xc1, xp + (kbase + 0) * BB);
            ldcg2(xn0, xn1, xp + (kbase + 1) * BB);
            #pragma unroll 1
            for (int k = 0; k < KCHUNK; k++) {
                ull xf0, xf1;
                const int kpf = (k + 2 < KCHUNK) ? (k + 2) : k;
                ldcg2(xf0, xf1, xp + (kbase + kpf) * BB);
                const ulonglong2* wp = wsv + (kbase + k) * 8;
                #pragma unroll
                for (int j = 0; j < 8; j++) {
                    const ulonglong2 w = wp[j];
                    acc[4 * j + 0] = ffma2(xc0, w.x, acc[4 * j + 0]);
                    acc[4 * j + 1] = ffma2(xc1, w.x, acc[4 * j + 1]);
                    acc[4 * j + 2] = ffma2(xc0, w.y, acc[4 * j + 2]);
                    acc[4 * j + 3] = ffma2(xc1, w.y, acc[4 * j + 3]);
                }
                xc0 = xn0; xc1 = xn1; xn0 = xf0; xn1 = xf1;
            }
        }
        // k-split reduction (ks 1..3 dump, ks 0 reduces)
        if (ks > 0) {
            ull* rp = &sm->u.red[((ks - 1) * 64 + bt) * 33];
            #pragma unroll
            for (int i = 0; i < 32; i++) rp[i] = acc[i];
        }
        __syncthreads();
        if (ks == 0) {
            #pragma unroll
            for (int rr = 0; rr < 3; rr++) {
                const ull* rp = &sm->u.red[(rr * 64 + bt) * 33];
                #pragma unroll
                for (int i = 0; i < 32; i++) acc[i] = addf2(acc[i], rp[i]);
            }
            // pointwise LSTM for 4 cols x 4 batches
            #pragma unroll
            for (int cl = 0; cl < 4; cl++) {
                float hv[4], cv[4];
                #pragma unroll
                for (int jj = 0; jj < 4; jj++) {
                    const int hf = jj >> 1, hi = jj & 1;
                    const int oi = cl * 4;
                    const float gi = (hi ? f2hi(acc[2 * (oi + 0) + hf]) : f2lo(acc[2 * (oi + 0) + hf])) + biasv[oi + 0];
                    const float gf = (hi ? f2hi(acc[2 * (oi + 1) + hf]) : f2lo(acc[2 * (oi + 1) + hf])) + biasv[oi + 1];
                    const float gg = (hi ? f2hi(acc[2 * (oi + 2) + hf]) : f2lo(acc[2 * (oi + 2) + hf])) + biasv[oi + 2];
                    const float go = (hi ? f2hi(acc[2 * (oi + 3) + hf]) : f2lo(acc[2 * (oi + 3) + hf])) + biasv[oi + 3];
                    const float cn = sigm(gf) * creg[cl * 4 + jj] + sigm(gi) * tanha(gg);
                    const float hn = sigm(go) * tanha(cn);
                    creg[cl * 4 + jj] = cn;
                    cv[jj] = cn; hv[jj] = hn;
                }
                const int col = c0 + cl;
                *(float4*)&XtW[col * BB + b0] = make_float4(hv[0], hv[1], hv[2], hv[3]);
                *(float4*)&g_Ct[col * BB + b0] = make_float4(cv[0], cv[1], cv[2], cv[3]);
                #pragma unroll
                for (int jj = 0; jj < 4; jj++)
                    out[((b0 + jj) * TT + t) * HH + col] = hv[jj];
            }
        }
        if (t < TT - 1) grid_sync();   // h(t), c(t) visible for next phase A
    }
}

// ---------------- launch ----------------
extern "C" void kernel_launch(void* const* d_in, const int* in_sizes, int n_in,
                              void* d_out, int out_size)
{
    const float* dx   = (const float*)d_in[0];
    const float* W_a1 = (const float*)d_in[1];
    const float* b_a1 = (const float*)d_in[2];
    const float* W_a2 = (const float*)d_in[3];
    const float* b_a2 = (const float*)d_in[4];
    const float* W_a3 = (const float*)d_in[5];
    const float* b_a3 = (const float*)d_in[6];
    const float* W_ih = (const float*)d_in[7];
    const float* W_hh = (const float*)d_in[8];
    const float* b_ih = (const float*)d_in[9];
    const float* b_hh = (const float*)d_in[10];
    float* out = (float*)d_out;

    const size_t smem = sizeof(SmemMain);
    cudaFuncSetAttribute(attn_lstm_kernel,
                         cudaFuncAttributeMaxDynamicSharedMemorySize, (int)smem);
    attn_lstm_kernel<<<GRID, NTHREADS, smem>>>(dx, W_a1, b_a1, W_a2, b_a2, W_a3,
                                               b_a3, W_ih, W_hh, b_ih, b_hh, out);
}

// round 4
// speedup vs baseline: 1.4147x; 1.2205x over previous
#include <cuda_runtime.h>
#include <cuda_bf16.h>
#include <cstdint>

#define GRID     128
#define NTHREADS 256
#define BB   256
#define TT   64
#define NIN  128
#define HH   512
#define KTOT 640
#define KCHUNK 32
#define NCHUNK (KTOT / KCHUNK)   // 20
#define XPAD 260                 // padded batch stride for staged x tiles

typedef unsigned long long ull;

// ---------------- global scratch ----------------
__device__ __align__(16) float g_z2[BB * TT * NIN];   // [b][s][n]
__device__ __align__(16) float g_Xt[2][KTOT * BB];    // [buf][k][b]
__device__ __align__(16) float g_Ct[HH * BB];         // [k][b]
__device__ __align__(16) __nv_bfloat16 g_wa1h[TT * 1024];  // bf16 W_a1 [s][k]
__device__ unsigned g_cnt = 0;
__device__ unsigned g_gen = 0;

// ---------------- shared ----------------
struct SmemMain {
    ull ws[KTOT * 16];                         // 80KB dup (w,w) weights [k][o]
    union {
        float xs[2][KCHUNK * XPAD];            // ~65KB staged x tiles (padded rows)
        struct { float dxs[TT * NIN]; float wa2s[TT * TT]; } pre;
    } u;
    float hss[2][1024];                        // 8KB staged [h|c]
    float z1s[2][TT];
    float wa3s[TT];
    float ba1s[TT];
    float redm[8];
    float reds[8];
    float ba3v;
};

// ---------------- helpers ----------------
__device__ __forceinline__ ull ffma2(ull a, ull b, ull c) {
    ull d; asm("fma.rn.f32x2 %0, %1, %2, %3;" : "=l"(d) : "l"(a), "l"(b), "l"(c)); return d;
}
__device__ __forceinline__ float f2lo(ull a) { return __uint_as_float((unsigned)(a & 0xffffffffull)); }
__device__ __forceinline__ float f2hi(ull a) { return __uint_as_float((unsigned)(a >> 32)); }
__device__ __forceinline__ ull dupf(float w) {
    unsigned b = __float_as_uint(w); return ((ull)b << 32) | (ull)b;
}
__device__ __forceinline__ float tanha(float x) {
    float y; asm("tanh.approx.f32 %0, %1;" : "=f"(y) : "f"(x)); return y;
}
__device__ __forceinline__ float sigm(float x) { return 0.5f * tanha(0.5f * x) + 0.5f; }
__device__ __forceinline__ float ldcgf(const float* p) {
    float v; asm volatile("ld.global.cg.f32 %0, [%1];" : "=f"(v) : "l"(p)); return v;
}
__device__ __forceinline__ void stcsf(float* p, float v) {
    asm volatile("st.global.cs.f32 [%0], %1;" :: "l"(p), "f"(v));
}
__device__ __forceinline__ void cpasync16(unsigned saddr, const float* g) {
    asm volatile("cp.async.cg.shared.global [%0], [%1], 16;" :: "r"(saddr), "l"(g));
}

__device__ __forceinline__ void grid_sync() {
    __threadfence();
    __syncthreads();
    if (threadIdx.x == 0) {
        unsigned gen = *((volatile unsigned*)&g_gen);
        if (atomicAdd(&g_cnt, 1u) == GRID - 1) {
            g_cnt = 0;
            __threadfence();
            atomicAdd(&g_gen, 1u);
        } else {
            while (*((volatile unsigned*)&g_gen) == gen) { __nanosleep(32); }
        }
    }
    __syncthreads();
}

// ---------------- kernel ----------------
__global__ void __launch_bounds__(NTHREADS, 1)
attn_lstm_kernel(const float* __restrict__ dx,   const float* __restrict__ W_a1,
                 const float* __restrict__ b_a1, const float* __restrict__ W_a2,
                 const float* __restrict__ b_a2, const float* __restrict__ W_a3,
                 const float* __restrict__ b_a3, const float* __restrict__ W_ih,
                 const float* __restrict__ W_hh, const float* __restrict__ b_ih,
                 const float* __restrict__ b_hh, float* __restrict__ out)
{
    extern __shared__ char smem_raw[];
    SmemMain* sm = (SmemMain*)smem_raw;

    const int tid  = threadIdx.x;
    const int bid  = blockIdx.x;
    const int lane = tid & 31;
    const int wid  = tid >> 5;

    // ---- init: zero h(-1)/c(-1); convert W_a1 to bf16
    for (int idx = bid * NTHREADS + tid; idx < KTOT * BB; idx += GRID * NTHREADS)
        g_Xt[0][idx] = 0.f;
    for (int idx = bid * NTHREADS + tid; idx < HH * BB; idx += GRID * NTHREADS)
        g_Ct[idx] = 0.f;
    for (int idx = bid * NTHREADS + tid; idx < TT * 1024; idx += GRID * NTHREADS)
        g_wa1h[idx] = __float2bfloat16(W_a1[idx]);

    // ---- weight-stationary slice: 4 cols (16 outputs), o = col_local*4 + gate
    const int c0 = bid * 4;
    for (int idx = tid; idx < KTOT * 16; idx += NTHREADS) {
        const int k = idx >> 4, o = idx & 15;
        const int col = c0 + (o >> 2), gate = o & 3;
        const int row = gate * HH + col;
        const float w = (k < HH) ? W_hh[row * HH + k] : W_ih[row * NIN + (k - HH)];
        sm->ws[idx] = dupf(w);
    }

    // ---- z2 precompute: z2[b][s][n] = sum_t dx[b][t][n]*W_a2[s][t] + b_a2[s]
    for (int idx = tid; idx < TT * TT; idx += NTHREADS) sm->u.pre.wa2s[idx] = W_a2[idx];
    for (int bh = 0; bh < 2; bh++) {
        const int b = bid + bh * GRID;
        __syncthreads();
        for (int idx = tid; idx < TT * NIN; idx += NTHREADS)
            sm->u.pre.dxs[idx] = dx[b * TT * NIN + idx];
        __syncthreads();
        const int q  = wid >> 2;
        const int n  = ((wid & 3) << 5) + lane;
        const int s0 = q << 5;
        float acc[32];
        #pragma unroll
        for (int j = 0; j < 32; j++) acc[j] = b_a2[s0 + j];
        for (int t = 0; t < TT; t++) {
            const float xv = sm->u.pre.dxs[t * NIN + n];
            #pragma unroll
            for (int j = 0; j < 32; j++) acc[j] += xv * sm->u.pre.wa2s[(s0 + j) * TT + t];
        }
        #pragma unroll
        for (int j = 0; j < 32; j++)
            g_z2[(b * TT + s0 + j) * NIN + n] = acc[j];
    }
    __syncthreads();

    // ---- small constants
    if (tid < TT) { sm->wa3s[tid] = W_a3[tid]; sm->ba1s[tid] = b_a1[tid]; }
    if (tid == 64) sm->ba3v = b_a3[0];

    // ---- phase-B thread identity: 128 batch-threads x 2 output-groups
    const int bt = tid & 127;
    const int og = tid >> 7;           // outputs og*8 .. og*8+7
    const int b0 = bt * 2;

    float biasv[8], creg[4];
    #pragma unroll
    for (int oo = 0; oo < 8; oo++) {
        const int o = og * 8 + oo;
        const int col = c0 + (o >> 2), gate = o & 3;
        biasv[oo] = b_ih[gate * HH + col] + b_hh[gate * HH + col];
    }
    #pragma unroll
    for (int j = 0; j < 4; j++) creg[j] = 0.f;

    const unsigned xs_base0 = (unsigned)__cvta_generic_to_shared(&sm->u.xs[0][0]);
    const unsigned xs_base1 = (unsigned)__cvta_generic_to_shared(&sm->u.xs[1][0]);

    grid_sync();   // init + z2 + wa1h visible

    // ================= main recurrence =================
    for (int t = 0; t < TT; t++) {
        const int r = t & 1;
        float* XtR = g_Xt[r];
        float* XtW = g_Xt[r ^ 1];

        // ===== Phase A =====
        for (int idx = tid; idx < 2048; idx += NTHREADS) {
            const int bh = idx >> 10, kk = idx & 1023;
            const int b = bid + bh * GRID;
            sm->hss[bh][kk] = (kk < HH) ? ldcgf(&XtR[kk * BB + b])
                                        : ldcgf(&g_Ct[(kk - HH) * BB + b]);
        }
        __syncthreads();
        {   // z1: warp -> 8 s-rows for both batches, bf16 weights, rows interleaved
            const int s0 = wid << 3;
            float a0[8], a1[8];
            #pragma unroll
            for (int j = 0; j < 8; j++) { a0[j] = 0.f; a1[j] = 0.f; }
            const unsigned* wr = (const unsigned*)&g_wa1h[s0 * 1024];   // bf162 rows
            const float2* h0p = (const float2*)sm->hss[0];
            const float2* h1p = (const float2*)sm->hss[1];
            #pragma unroll 2
            for (int it = 0; it < 16; it++) {
                const int kk = it * 32 + lane;       // bf162 index
                const float2 h0 = h0p[kk];
                const float2 h1 = h1p[kk];
                #pragma unroll
                for (int j = 0; j < 8; j++) {
                    const unsigned w = wr[j * 512 + kk];
                    const float wlo = __uint_as_float(w << 16);
                    const float whi = __uint_as_float(w & 0xffff0000u);
                    a0[j] += wlo * h0.x + whi * h0.y;
                    a1[j] += wlo * h1.x + whi * h1.y;
                }
            }
            #pragma unroll
            for (int j = 0; j < 8; j++) {
                #pragma unroll
                for (int off = 16; off; off >>= 1) {
                    a0[j] += __shfl_xor_sync(0xffffffffu, a0[j], off);
                    a1[j] += __shfl_xor_sync(0xffffffffu, a1[j], off);
                }
                if (lane == 0) {
                    sm->z1s[0][s0 + j] = a0[j] + sm->ba1s[s0 + j];
                    sm->z1s[1][s0 + j] = a1[j] + sm->ba1s[s0 + j];
                }
            }
        }
        __syncthreads();
        {   // e + softmax + wx
            const int bh = tid >> 7, n = tid & 127;
            const int b = bid + bh * GRID;
            const float* zp = &g_z2[(b * TT) * NIN + n];
            const float* z1p = sm->z1s[bh];
            float e = sm->ba3v;
            #pragma unroll 16
            for (int s = 0; s < TT; s++)
                e += tanha(z1p[s] + zp[s * NIN]) * sm->wa3s[s];
            const float xv = dx[(b * TT + t) * NIN + n];
            float m = e;
            #pragma unroll
            for (int off = 16; off; off >>= 1) m = fmaxf(m, __shfl_xor_sync(0xffffffffu, m, off));
            if (lane == 0) sm->redm[wid] = m;
            __syncthreads();
            const int wb = bh * 4;
            const float m4 = fmaxf(fmaxf(sm->redm[wb], sm->redm[wb + 1]),
                                   fmaxf(sm->redm[wb + 2], sm->redm[wb + 3]));
            const float p = __expf(e - m4);
            float ssum = p;
            #pragma unroll
            for (int off = 16; off; off >>= 1) ssum += __shfl_xor_sync(0xffffffffu, ssum, off);
            if (lane == 0) sm->reds[wid] = ssum;
            __syncthreads();
            const float tot = sm->reds[wb] + sm->reds[wb + 1] + sm->reds[wb + 2] + sm->reds[wb + 3];
            XtR[(HH + n) * BB + b] = (p / tot) * xv;
        }
        grid_sync();   // wx visible

        // ===== Phase B: smem-staged gates GEMM =====
        ull acc[8];
        #pragma unroll
        for (int i = 0; i < 8; i++) acc[i] = 0ull;

        // stage chunk 0 (64 rows of 256 floats -> padded rows of XPAD)
        {
            const float* src = XtR;
            for (int i = tid; i < (KCHUNK * BB) / 4; i += NTHREADS) {
                const int kk = i >> 6, bq = i & 63;      // row, float4-within-row
                cpasync16(xs_base0 + (kk * XPAD + bq * 4) * 4, src + i * 4);
            }
            asm volatile("cp.async.commit_group;");
        }
        for (int c = 0; c < NCHUNK; c++) {
            if (c + 1 < NCHUNK) {
                const float* src = XtR + (c + 1) * KCHUNK * BB;
                const unsigned dst = ((c + 1) & 1) ? xs_base1 : xs_base0;
                for (int i = tid; i < (KCHUNK * BB) / 4; i += NTHREADS) {
                    const int kk = i >> 6, bq = i & 63;
                    cpasync16(dst + (kk * XPAD + bq * 4) * 4, src + i * 4);
                }
                asm volatile("cp.async.commit_group;");
                asm volatile("cp.async.wait_group 1;");
            } else {
                asm volatile("cp.async.wait_group 0;");
            }
            __syncthreads();
            {
                const float* xp = &sm->u.xs[c & 1][b0];
                const ulonglong2* wp = (const ulonglong2*)&sm->ws[(c * KCHUNK) * 16 + og * 8];
                #pragma unroll 8
                for (int kl = 0; kl < KCHUNK; kl++) {
                    const ull x = *(const ull*)(xp + kl * XPAD);
                    const ulonglong2 w0 = wp[kl * 8 + 0];
                    const ulonglong2 w1 = wp[kl * 8 + 1];
                    const ulonglong2 w2 = wp[kl * 8 + 2];
                    const ulonglong2 w3 = wp[kl * 8 + 3];
                    acc[0] = ffma2(x, w0.x, acc[0]);
                    acc[1] = ffma2(x, w0.y, acc[1]);
                    acc[2] = ffma2(x, w1.x, acc[2]);
                    acc[3] = ffma2(x, w1.y, acc[3]);
                    acc[4] = ffma2(x, w2.x, acc[4]);
                    acc[5] = ffma2(x, w2.y, acc[5]);
                    acc[6] = ffma2(x, w3.x, acc[6]);
                    acc[7] = ffma2(x, w3.y, acc[7]);
                }
            }
            __syncthreads();
        }

        // pointwise LSTM: 2 cols x 2 batches per thread, full dot products in acc
        #pragma unroll
        for (int cl = 0; cl < 2; cl++) {
            const int o4 = cl * 4;
            float hv[2], cv[2];
            #pragma unroll
            for (int j = 0; j < 2; j++) {
                const float gi = (j ? f2hi(acc[o4 + 0]) : f2lo(acc[o4 + 0])) + biasv[o4 + 0];
                const float gf = (j ? f2hi(acc[o4 + 1]) : f2lo(acc[o4 + 1])) + biasv[o4 + 1];
                const float gg = (j ? f2hi(acc[o4 + 2]) : f2lo(acc[o4 + 2])) + biasv[o4 + 2];
                const float go = (j ? f2hi(acc[o4 + 3]) : f2lo(acc[o4 + 3])) + biasv[o4 + 3];
                const float cn = sigm(gf) * creg[cl * 2 + j] + sigm(gi) * tanha(gg);
                const float hn = sigm(go) * tanha(cn);
                creg[cl * 2 + j] = cn;
                cv[j] = cn; hv[j] = hn;
            }
            const int col = c0 + og * 2 + cl;
            *(float2*)&XtW[col * BB + b0] = make_float2(hv[0], hv[1]);
            *(float2*)&g_Ct[col * BB + b0] = make_float2(cv[0], cv[1]);
            stcsf(&out[(b0 * TT + t) * HH + col],       hv[0]);
            stcsf(&out[((b0 + 1) * TT + t) * HH + col], hv[1]);
        }
        if (t < TT - 1) grid_sync();   // h(t), c(t) visible
    }
}

// ---------------- launch ----------------
extern "C" void kernel_launch(void* const* d_in, const int* in_sizes, int n_in,
                              void* d_out, int out_size)
{
    const float* dx   = (const float*)d_in[0];
    const float* W_a1 = (const float*)d_in[1];
    const float* b_a1 = (const float*)d_in[2];
    const float* W_a2 = (const float*)d_in[3];
    const float* b_a2 = (const float*)d_in[4];
    const float* W_a3 = (const float*)d_in[5];
    const float* b_a3 = (const float*)d_in[6];
    const float* W_ih = (const float*)d_in[7];
    const float* W_hh = (const float*)d_in[8];
    const float* b_ih = (const float*)d_in[9];
    const float* b_hh = (const float*)d_in[10];
    float* out = (float*)d_out;

    const size_t smem = sizeof(SmemMain);
    cudaFuncSetAttribute(attn_lstm_kernel,
                         cudaFuncAttributeMaxDynamicSharedMemorySize, (int)smem);
    attn_lstm_kernel<<<GRID, NTHREADS, smem>>>(dx, W_a1, b_a1, W_a2, b_a2, W_a3,
                                               b_a3, W_ih, W_hh, b_ih, b_hh, out);
}

// round 7
// speedup vs baseline: 2.0201x; 1.4279x over previous
#include <cuda_runtime.h>
#include <cuda_bf16.h>
#include <cstdint>

#define GRID     128
#define NTHREADS 256
#define BB   256
#define TT   64
#define NIN  128
#define HH   512
#define KTOT 640
#define KCHUNK 64
#define NCHUNK (KTOT / KCHUNK)   // 10

typedef unsigned long long ull;

// ---------------- global scratch ----------------
__device__ __align__(16) float g_z2[BB * TT * NIN];   // [b][s][n]
__device__ __align__(16) float g_Xt[2][KTOT * BB];    // [buf][k][b]
__device__ __align__(16) float g_Hb[BB * HH];         // [b][k] h (for phase A)
__device__ __align__(16) float g_Cb[BB * HH];         // [b][k] c (for phase A)
__device__ __align__(16) __nv_bfloat16 g_wa1h[TT * 1024];  // bf16 W_a1 [s][k]
__device__ unsigned g_cnt = 0;
__device__ unsigned g_gen = 0;

// ---------------- shared ----------------
struct SmemMain {
    float ws[KTOT * 16];                       // 40KB scalar weights [k][o]
    union {
        float xs[2][KCHUNK * BB];              // 128KB staged x tiles
        struct { float dxs[TT * NIN]; float wa2s[TT * TT]; } pre;
    } u;
    float hss[2][1024];                        // 8KB staged [h|c]
    float z1s[2][TT];
    float wa3s[TT];
    float ba1s[TT];
    float redm[8];
    float reds[8];
    float ba3v;
};

// ---------------- helpers ----------------
__device__ __forceinline__ ull ffma2(ull a, ull b, ull c) {
    ull d; asm("fma.rn.f32x2 %0, %1, %2, %3;" : "=l"(d) : "l"(a), "l"(b), "l"(c)); return d;
}
__device__ __forceinline__ float f2lo(ull a) { return __uint_as_float((unsigned)(a & 0xffffffffull)); }
__device__ __forceinline__ float f2hi(ull a) { return __uint_as_float((unsigned)(a >> 32)); }
__device__ __forceinline__ ull dupf(float x) {
    ull d; unsigned r = __float_as_uint(x);
    asm("mov.b64 %0, {%1, %1};" : "=l"(d) : "r"(r));
    return d;
}
__device__ __forceinline__ float tanha(float x) {
    float y; asm("tanh.approx.f32 %0, %1;" : "=f"(y) : "f"(x)); return y;
}
__device__ __forceinline__ float sigm(float x) { return 0.5f * tanha(0.5f * x) + 0.5f; }
__device__ __forceinline__ float4 ldcg4(const float* p) {
    float4 v;
    asm volatile("ld.global.cg.v4.f32 {%0,%1,%2,%3}, [%4];"
                 : "=f"(v.x), "=f"(v.y), "=f"(v.z), "=f"(v.w) : "l"(p));
    return v;
}
__device__ __forceinline__ void stcs2(float* p, float a, float b) {
    asm volatile("st.global.cs.v2.f32 [%0], {%1,%2};" :: "l"(p), "f"(a), "f"(b));
}
__device__ __forceinline__ void cpasync16(unsigned saddr, const float* g) {
    asm volatile("cp.async.cg.shared.global [%0], [%1], 16;" :: "r"(saddr), "l"(g));
}

__device__ __forceinline__ void grid_sync() {
    __threadfence();
    __syncthreads();
    if (threadIdx.x == 0) {
        unsigned gen = *((volatile unsigned*)&g_gen);
        if (atomicAdd(&g_cnt, 1u) == GRID - 1) {
            g_cnt = 0;
            __threadfence();
            atomicAdd(&g_gen, 1u);
        } else {
            while (*((volatile unsigned*)&g_gen) == gen) {}
        }
    }
    __syncthreads();
}

// ---------------- kernel ----------------
__global__ void __launch_bounds__(NTHREADS, 1)
attn_lstm_kernel(const float* __restrict__ dx,   const float* __restrict__ W_a1,
                 const float* __restrict__ b_a1, const float* __restrict__ W_a2,
                 const float* __restrict__ b_a2, const float* __restrict__ W_a3,
                 const float* __restrict__ b_a3, const float* __restrict__ W_ih,
                 const float* __restrict__ W_hh, const float* __restrict__ b_ih,
                 const float* __restrict__ b_hh, float* __restrict__ out)
{
    extern __shared__ char smem_raw[];
    SmemMain* sm = (SmemMain*)smem_raw;

    const int tid  = threadIdx.x;
    const int bid  = blockIdx.x;
    const int lane = tid & 31;
    const int wid  = tid >> 5;

    // ---- init: zero h(-1)/c(-1) in all layouts; convert W_a1 to bf16
    for (int idx = bid * NTHREADS + tid; idx < HH * BB; idx += GRID * NTHREADS) {
        g_Xt[0][idx] = 0.f;
        g_Hb[idx] = 0.f;
        g_Cb[idx] = 0.f;
    }
    for (int idx = bid * NTHREADS + tid; idx < TT * 1024; idx += GRID * NTHREADS)
        g_wa1h[idx] = __float2bfloat16(W_a1[idx]);

    // ---- weight-stationary slice: 4 cols (16 outputs), o = (og*2+cl)*4 + gate
    const int c0 = bid * 4;
    for (int idx = tid; idx < KTOT * 16; idx += NTHREADS) {
        const int k = idx >> 4, o = idx & 15;
        const int col = c0 + (o >> 2), gate = o & 3;
        const int row = gate * HH + col;
        sm->ws[idx] = (k < HH) ? W_hh[row * HH + k] : W_ih[row * NIN + (k - HH)];
    }

    // ---- z2 precompute: z2[b][s][n] = sum_t dx[b][t][n]*W_a2[s][t] + b_a2[s]
    for (int idx = tid; idx < TT * TT; idx += NTHREADS) sm->u.pre.wa2s[idx] = W_a2[idx];
    for (int bh = 0; bh < 2; bh++) {
        const int b = bid + bh * GRID;
        __syncthreads();
        for (int idx = tid; idx < TT * NIN; idx += NTHREADS)
            sm->u.pre.dxs[idx] = dx[b * TT * NIN + idx];
        __syncthreads();
        const int q  = wid >> 2;
        const int n  = ((wid & 3) << 5) + lane;
        const int s0 = q << 5;
        float acc[32];
        #pragma unroll
        for (int j = 0; j < 32; j++) acc[j] = b_a2[s0 + j];
        for (int t = 0; t < TT; t++) {
            const float xv = sm->u.pre.dxs[t * NIN + n];
            #pragma unroll
            for (int j = 0; j < 32; j++) acc[j] += xv * sm->u.pre.wa2s[(s0 + j) * TT + t];
        }
        #pragma unroll
        for (int j = 0; j < 32; j++)
            g_z2[(b * TT + s0 + j) * NIN + n] = acc[j];
    }
    __syncthreads();

    // ---- small constants
    if (tid < TT) { sm->wa3s[tid] = W_a3[tid]; sm->ba1s[tid] = b_a1[tid]; }
    if (tid == 64) sm->ba3v = b_a3[0];

    // ---- phase-B thread identity: 128 batch-threads x 2 output-groups
    const int bt = tid & 127;
    const int og = tid >> 7;           // cols c0+og*2, c0+og*2+1
    const int b0 = bt * 2;             // 2 batches (scalar x each)

    float biasv[8], creg[4];
    #pragma unroll
    for (int oo = 0; oo < 8; oo++) {
        const int col = c0 + og * 2 + (oo >> 2), gate = oo & 3;
        biasv[oo] = b_ih[gate * HH + col] + b_hh[gate * HH + col];
    }
    #pragma unroll
    for (int j = 0; j < 4; j++) creg[j] = 0.f;

    const unsigned xs_base0 = (unsigned)__cvta_generic_to_shared(&sm->u.xs[0][0]);
    const unsigned xs_base1 = (unsigned)__cvta_generic_to_shared(&sm->u.xs[1][0]);

    grid_sync();   // init + z2 + wa1h visible

    // ================= main recurrence =================
    for (int t = 0; t < TT; t++) {
        const int r = t & 1;
        float* XtR = g_Xt[r];
        float* XtW = g_Xt[r ^ 1];

        // ===== Phase A =====
        // stage [h|c] for 2 batches from [b][k] layouts (coalesced .cg float4)
        for (int idx = tid; idx < 512; idx += NTHREADS) {
            const int bh = idx >> 8, q = idx & 255;
            const int b = bid + bh * GRID;
            const float4 v = (q < 128) ? ldcg4(&g_Hb[b * HH + q * 4])
                                       : ldcg4(&g_Cb[b * HH + (q - 128) * 4]);
            *(float4*)&sm->hss[bh][q * 4] = v;
        }
        __syncthreads();
        {   // z1: warp -> 8 s-rows for both batches, bf16 weights, rows interleaved
            const int s0 = wid << 3;
            float a0[8], a1[8];
            #pragma unroll
            for (int j = 0; j < 8; j++) { a0[j] = 0.f; a1[j] = 0.f; }
            const unsigned* wr = (const unsigned*)&g_wa1h[s0 * 1024];   // bf162 rows
            const float2* h0p = (const float2*)sm->hss[0];
            const float2* h1p = (const float2*)sm->hss[1];
            #pragma unroll 2
            for (int it = 0; it < 16; it++) {
                const int kk = it * 32 + lane;       // bf162 index
                const float2 h0 = h0p[kk];
                const float2 h1 = h1p[kk];
                #pragma unroll
                for (int j = 0; j < 8; j++) {
                    const unsigned w = wr[j * 512 + kk];
                    const float wlo = __uint_as_float(w << 16);
                    const float whi = __uint_as_float(w & 0xffff0000u);
                    a0[j] += wlo * h0.x + whi * h0.y;
                    a1[j] += wlo * h1.x + whi * h1.y;
                }
            }
            #pragma unroll
            for (int j = 0; j < 8; j++) {
                #pragma unroll
                for (int off = 16; off; off >>= 1) {
                    a0[j] += __shfl_xor_sync(0xffffffffu, a0[j], off);
                    a1[j] += __shfl_xor_sync(0xffffffffu, a1[j], off);
                }
                if (lane == 0) {
                    sm->z1s[0][s0 + j] = a0[j] + sm->ba1s[s0 + j];
                    sm->z1s[1][s0 + j] = a1[j] + sm->ba1s[s0 + j];
                }
            }
        }
        __syncthreads();
        {   // e + softmax + wx
            const int bh = tid >> 7, n = tid & 127;
            const int b = bid + bh * GRID;
            const float* zp = &g_z2[(b * TT) * NIN + n];
            const float* z1p = sm->z1s[bh];
            float e = sm->ba3v;
            #pragma unroll 16
            for (int s = 0; s < TT; s++)
                e += tanha(z1p[s] + zp[s * NIN]) * sm->wa3s[s];
            const float xv = dx[(b * TT + t) * NIN + n];
            float m = e;
            #pragma unroll
            for (int off = 16; off; off >>= 1) m = fmaxf(m, __shfl_xor_sync(0xffffffffu, m, off));
            if (lane == 0) sm->redm[wid] = m;
            __syncthreads();
            const int wb = bh * 4;
            const float m4 = fmaxf(fmaxf(sm->redm[wb], sm->redm[wb + 1]),
                                   fmaxf(sm->redm[wb + 2], sm->redm[wb + 3]));
            const float p = __expf(e - m4);
            float ssum = p;
            #pragma unroll
            for (int off = 16; off; off >>= 1) ssum += __shfl_xor_sync(0xffffffffu, ssum, off);
            if (lane == 0) sm->reds[wid] = ssum;
            __syncthreads();
            const float tot = sm->reds[wb] + sm->reds[wb + 1] + sm->reds[wb + 2] + sm->reds[wb + 3];
            XtR[(HH + n) * BB + b] = (p / tot) * xv;
        }
        grid_sync();   // wx visible

        // ===== Phase B: smem-staged gates GEMM, output-paired FFMA2 =====
        ull acc[8];     // [batch j (2)][col cl (2)][pair: (i,f) / (g,o)]
        #pragma unroll
        for (int i = 0; i < 8; i++) acc[i] = 0ull;

        // stage chunk 0
        {
            const float* src = XtR;
            for (int i = tid; i < (KCHUNK * BB) / 4; i += NTHREADS)
                cpasync16(xs_base0 + i * 16, src + i * 4);
            asm volatile("cp.async.commit_group;");
        }
        for (int c = 0; c < NCHUNK; c++) {
            if (c + 1 < NCHUNK) {
                const float* src = XtR + (c + 1) * KCHUNK * BB;
                const unsigned dst = ((c + 1) & 1) ? xs_base1 : xs_base0;
                for (int i = tid; i < (KCHUNK * BB) / 4; i += NTHREADS)
                    cpasync16(dst + i * 16, src + i * 4);
                asm volatile("cp.async.commit_group;");
                asm volatile("cp.async.wait_group 1;");
            } else {
                asm volatile("cp.async.wait_group 0;");
            }
            __syncthreads();
            {
                const float* xp = &sm->u.xs[c & 1][b0];
                // 16 floats per k = 4 ulonglong2; base already offset by og*8 floats
                const ulonglong2* wp = (const ulonglong2*)&sm->ws[(c * KCHUNK) * 16 + og * 8];
                #pragma unroll 8
                for (int kl = 0; kl < KCHUNK; kl++) {
                    const float2 xv = *(const float2*)(xp + kl * BB);
                    const ull xd0 = dupf(xv.x);
                    const ull xd1 = dupf(xv.y);
                    const ulonglong2 wA = wp[kl * 4 + 0];   // col cl=0: (wi,wf),(wg,wo)
                    const ulonglong2 wB = wp[kl * 4 + 1];   // col cl=1
                    acc[0] = ffma2(xd0, wA.x, acc[0]);
                    acc[1] = ffma2(xd0, wA.y, acc[1]);
                    acc[2] = ffma2(xd0, wB.x, acc[2]);
                    acc[3] = ffma2(xd0, wB.y, acc[3]);
                    acc[4] = ffma2(xd1, wA.x, acc[4]);
                    acc[5] = ffma2(xd1, wA.y, acc[5]);
                    acc[6] = ffma2(xd1, wB.x, acc[6]);
                    acc[7] = ffma2(xd1, wB.y, acc[7]);
                }
            }
            __syncthreads();
        }

        // pointwise LSTM: 2 batches x 2 cols per thread
        float hvv[2][2], cvv[2][2];
        #pragma unroll
        for (int j = 0; j < 2; j++) {
            #pragma unroll
            for (int cl = 0; cl < 2; cl++) {
                const ull aif = acc[j * 4 + cl * 2 + 0];
                const ull ago = acc[j * 4 + cl * 2 + 1];
                const float gi = f2lo(aif) + biasv[cl * 4 + 0];
                const float gf = f2hi(aif) + biasv[cl * 4 + 1];
                const float gg = f2lo(ago) + biasv[cl * 4 + 2];
                const float go = f2hi(ago) + biasv[cl * 4 + 3];
                const float cn = sigm(gf) * creg[j * 2 + cl] + sigm(gi) * tanha(gg);
                const float hn = sigm(go) * tanha(cn);
                creg[j * 2 + cl] = cn;
                cvv[j][cl] = cn; hvv[j][cl] = hn;
            }
        }
        {
            const int colb = c0 + og * 2;
            #pragma unroll
            for (int cl = 0; cl < 2; cl++)    // [k][b] layout for next GEMM
                *(float2*)&XtW[(colb + cl) * BB + b0] = make_float2(hvv[0][cl], hvv[1][cl]);
            #pragma unroll
            for (int j = 0; j < 2; j++) {     // [b][k] layouts for next phase A
                const int b = b0 + j;
                *(float2*)&g_Hb[b * HH + colb] = make_float2(hvv[j][0], hvv[j][1]);
                *(float2*)&g_Cb[b * HH + colb] = make_float2(cvv[j][0], cvv[j][1]);
                stcs2(&out[(b * TT + t) * HH + colb], hvv[j][0], hvv[j][1]);
            }
        }
        if (t < TT - 1) grid_sync();   // h(t), c(t) visible
    }
}

// ---------------- launch ----------------
extern "C" void kernel_launch(void* const* d_in, const int* in_sizes, int n_in,
                              void* d_out, int out_size)
{
    const float* dx   = (const float*)d_in[0];
    const float* W_a1 = (const float*)d_in[1];
    const float* b_a1 = (const float*)d_in[2];
    const float* W_a2 = (const float*)d_in[3];
    const float* b_a2 = (const float*)d_in[4];
    const float* W_a3 = (const float*)d_in[5];
    const float* b_a3 = (const float*)d_in[6];
    const float* W_ih = (const float*)d_in[7];
    const float* W_hh = (const float*)d_in[8];
    const float* b_ih = (const float*)d_in[9];
    const float* b_hh = (const float*)d_in[10];
    float* out = (float*)d_out;

    const size_t smem = sizeof(SmemMain);
    cudaFuncSetAttribute(attn_lstm_kernel,
                         cudaFuncAttributeMaxDynamicSharedMemorySize, (int)smem);
    attn_lstm_kernel<<<GRID, NTHREADS, smem>>>(dx, W_a1, b_a1, W_a2, b_a2, W_a3,
                                               b_a3, W_ih, W_hh, b_ih, b_hh, out);
}

// round 8
// speedup vs baseline: 2.1075x; 1.0433x over previous
#include <cuda_runtime.h>
#include <cuda_bf16.h>
#include <cstdint>

#define GRID     128
#define NTHREADS 256
#define BB   256
#define TT   64
#define NIN  128
#define HH   512
#define KTOT 640
#define KCHUNK 80
#define NCHUNK (KTOT / KCHUNK)   // 8

typedef unsigned long long ull;

// ---------------- global scratch ----------------
__device__ __align__(16) float g_z2[BB * TT * NIN];   // [b][s][n]
__device__ __align__(16) float g_Xt[2][KTOT * BB];    // [buf][k][b]
__device__ __align__(16) float g_Hb[BB * HH];         // [b][k] h (for phase A)
__device__ __align__(16) float g_Cb[BB * HH];         // [b][k] c (for phase A)
__device__ __align__(16) __nv_bfloat16 g_wa1h[TT * 1024];  // bf16 W_a1 [s][k]
__device__ unsigned g_cnt = 0;
__device__ unsigned g_gen = 0;

// ---------------- shared ----------------
struct SmemMain {
    float ws[KTOT * 16];                       // 40KB scalar weights [k][o]
    union {
        float xs[2][KCHUNK * BB];              // 160KB staged x tiles / z2 slab in xs[0]
        struct { float dxs[TT * NIN]; float wa2s[TT * TT]; } pre;
    } u;
    float hss[2][1024];                        // 8KB staged [h|c]
    float z1s[2][TT];
    float wa3s[TT];
    float ba1s[TT];
    float reds[8];
    float ba3v;
};

// ---------------- helpers ----------------
__device__ __forceinline__ ull ffma2(ull a, ull b, ull c) {
    ull d; asm("fma.rn.f32x2 %0, %1, %2, %3;" : "=l"(d) : "l"(a), "l"(b), "l"(c)); return d;
}
__device__ __forceinline__ float f2lo(ull a) { return __uint_as_float((unsigned)(a & 0xffffffffull)); }
__device__ __forceinline__ float f2hi(ull a) { return __uint_as_float((unsigned)(a >> 32)); }
__device__ __forceinline__ ull dupf(float x) {
    ull d; unsigned r = __float_as_uint(x);
    asm("mov.b64 %0, {%1, %1};" : "=l"(d) : "r"(r));
    return d;
}
__device__ __forceinline__ float tanha(float x) {
    float y; asm("tanh.approx.f32 %0, %1;" : "=f"(y) : "f"(x)); return y;
}
__device__ __forceinline__ float sigm(float x) { return 0.5f * tanha(0.5f * x) + 0.5f; }
__device__ __forceinline__ void stcs2(float* p, float a, float b) {
    asm volatile("st.global.cs.v2.f32 [%0], {%1,%2};" :: "l"(p), "f"(a), "f"(b));
}
__device__ __forceinline__ void cpasync16(unsigned saddr, const float* g) {
    asm volatile("cp.async.cg.shared.global [%0], [%1], 16;" :: "r"(saddr), "l"(g));
}

__device__ __forceinline__ void grid_sync() {
    __threadfence();
    __syncthreads();
    if (threadIdx.x == 0) {
        unsigned gen = *((volatile unsigned*)&g_gen);
        if (atomicAdd(&g_cnt, 1u) == GRID - 1) {
            g_cnt = 0;
            __threadfence();
            atomicAdd(&g_gen, 1u);
        } else {
            while (*((volatile unsigned*)&g_gen) == gen) {}
        }
    }
    __syncthreads();
}

// ---------------- kernel ----------------
__global__ void __launch_bounds__(NTHREADS, 1)
attn_lstm_kernel(const float* __restrict__ dx,   const float* __restrict__ W_a1,
                 const float* __restrict__ b_a1, const float* __restrict__ W_a2,
                 const float* __restrict__ b_a2, const float* __restrict__ W_a3,
                 const float* __restrict__ b_a3, const float* __restrict__ W_ih,
                 const float* __restrict__ W_hh, const float* __restrict__ b_ih,
                 const float* __restrict__ b_hh, float* __restrict__ out)
{
    extern __shared__ char smem_raw[];
    SmemMain* sm = (SmemMain*)smem_raw;

    const int tid  = threadIdx.x;
    const int bid  = blockIdx.x;
    const int lane = tid & 31;
    const int wid  = tid >> 5;

    // ---- init: zero h(-1)/c(-1) in all layouts; convert W_a1 to bf16
    for (int idx = bid * NTHREADS + tid; idx < HH * BB; idx += GRID * NTHREADS) {
        g_Xt[0][idx] = 0.f;
        g_Hb[idx] = 0.f;
        g_Cb[idx] = 0.f;
    }
    for (int idx = bid * NTHREADS + tid; idx < TT * 1024; idx += GRID * NTHREADS)
        g_wa1h[idx] = __float2bfloat16(W_a1[idx]);

    // ---- weight-stationary slice: 4 cols (16 outputs), o = (og*2+cl)*4 + gate
    const int c0 = bid * 4;
    for (int idx = tid; idx < KTOT * 16; idx += NTHREADS) {
        const int k = idx >> 4, o = idx & 15;
        const int col = c0 + (o >> 2), gate = o & 3;
        const int row = gate * HH + col;
        sm->ws[idx] = (k < HH) ? W_hh[row * HH + k] : W_ih[row * NIN + (k - HH)];
    }

    // ---- z2 precompute: z2[b][s][n] = sum_t dx[b][t][n]*W_a2[s][t] + b_a2[s]
    for (int idx = tid; idx < TT * TT; idx += NTHREADS) sm->u.pre.wa2s[idx] = W_a2[idx];
    for (int bh = 0; bh < 2; bh++) {
        const int b = bid + bh * GRID;
        __syncthreads();
        for (int idx = tid; idx < TT * NIN; idx += NTHREADS)
            sm->u.pre.dxs[idx] = dx[b * TT * NIN + idx];
        __syncthreads();
        const int q  = wid >> 2;
        const int n  = ((wid & 3) << 5) + lane;
        const int s0 = q << 5;
        float acc[32];
        #pragma unroll
        for (int j = 0; j < 32; j++) acc[j] = b_a2[s0 + j];
        for (int t = 0; t < TT; t++) {
            const float xv = sm->u.pre.dxs[t * NIN + n];
            #pragma unroll
            for (int j = 0; j < 32; j++) acc[j] += xv * sm->u.pre.wa2s[(s0 + j) * TT + t];
        }
        #pragma unroll
        for (int j = 0; j < 32; j++)
            g_z2[(b * TT + s0 + j) * NIN + n] = acc[j];
    }
    __syncthreads();

    // ---- small constants
    if (tid < TT) { sm->wa3s[tid] = W_a3[tid]; sm->ba1s[tid] = b_a1[tid]; }
    if (tid == 64) sm->ba3v = b_a3[0];

    // ---- phase-B thread identity: 128 batch-threads x 2 output-groups
    const int bt = tid & 127;
    const int og = tid >> 7;           // cols c0+og*2, c0+og*2+1
    const int b0 = bt * 2;             // 2 batches (scalar x each)

    float biasv[8], creg[4];
    #pragma unroll
    for (int oo = 0; oo < 8; oo++) {
        const int col = c0 + og * 2 + (oo >> 2), gate = oo & 3;
        biasv[oo] = b_ih[gate * HH + col] + b_hh[gate * HH + col];
    }
    #pragma unroll
    for (int j = 0; j < 4; j++) creg[j] = 0.f;

    const unsigned xs_base0 = (unsigned)__cvta_generic_to_shared(&sm->u.xs[0][0]);
    const unsigned xs_base1 = (unsigned)__cvta_generic_to_shared(&sm->u.xs[1][0]);
    const unsigned hss_base = (unsigned)__cvta_generic_to_shared(&sm->hss[0][0]);

    grid_sync();   // init + z2 + wa1h visible

    // ================= main recurrence =================
    for (int t = 0; t < TT; t++) {
        const int r = t & 1;
        float* XtR = g_Xt[r];
        float* XtW = g_Xt[r ^ 1];

        // ===== Phase A =====
        // group 0: stage [h|c] (2 batches) via cp.async from [b][k] layouts
        for (int idx = tid; idx < 512; idx += NTHREADS) {
            const int bh = idx >> 8, q = idx & 255;
            const int b = bid + bh * GRID;
            const float* src = (q < 128) ? &g_Hb[b * HH + q * 4]
                                         : &g_Cb[b * HH + (q - 128) * 4];
            cpasync16(hss_base + idx * 16, src);
        }
        asm volatile("cp.async.commit_group;");
        // group 1: stage z2 slabs for both batches into xs[0] (64KB of 80KB)
        {
            float* zdst = sm->u.xs[0];
            for (int idx = tid; idx < 4096; idx += NTHREADS) {
                const int bh = idx >> 11, q = idx & 2047;   // q = float4 within slab
                const int b = bid + bh * GRID;
                cpasync16(xs_base0 + (bh * 8192 + q * 4) * 4,
                          &g_z2[b * TT * NIN + q * 4]);
            }
            (void)zdst;
        }
        asm volatile("cp.async.commit_group;");
        asm volatile("cp.async.wait_group 1;");   // hss ready (this thread)
        __syncthreads();                          // hss ready (all threads)
        {   // z1: warp -> 8 s-rows for both batches, bf16 weights, unroll 4 (MLP 32)
            const int s0 = wid << 3;
            float a0[8], a1[8];
            #pragma unroll
            for (int j = 0; j < 8; j++) { a0[j] = 0.f; a1[j] = 0.f; }
            const unsigned* wr = (const unsigned*)&g_wa1h[s0 * 1024];   // bf162 rows
            const float2* h0p = (const float2*)sm->hss[0];
            const float2* h1p = (const float2*)sm->hss[1];
            #pragma unroll 4
            for (int it = 0; it < 16; it++) {
                const int kk = it * 32 + lane;       // bf162 index
                const float2 h0 = h0p[kk];
                const float2 h1 = h1p[kk];
                #pragma unroll
                for (int j = 0; j < 8; j++) {
                    const unsigned w = wr[j * 512 + kk];
                    const float wlo = __uint_as_float(w << 16);
                    const float whi = __uint_as_float(w & 0xffff0000u);
                    a0[j] += wlo * h0.x + whi * h0.y;
                    a1[j] += wlo * h1.x + whi * h1.y;
                }
            }
            #pragma unroll
            for (int j = 0; j < 8; j++) {
                #pragma unroll
                for (int off = 16; off; off >>= 1) {
                    a0[j] += __shfl_xor_sync(0xffffffffu, a0[j], off);
                    a1[j] += __shfl_xor_sync(0xffffffffu, a1[j], off);
                }
                if (lane == 0) {
                    sm->z1s[0][s0 + j] = a0[j] + sm->ba1s[s0 + j];
                    sm->z1s[1][s0 + j] = a1[j] + sm->ba1s[s0 + j];
                }
            }
        }
        asm volatile("cp.async.wait_group 0;");   // z2 slab ready (this thread)
        __syncthreads();                          // z1s + z2 slab ready (all)
        {   // e + softmax (no max-sub; |e| <= ~9 so expf is safe) + wx
            const int bh = tid >> 7, n = tid & 127;
            const int b = bid + bh * GRID;
            const float* zp = &sm->u.xs[0][bh * 8192 + n];
            const float* z1p = sm->z1s[bh];
            float e = sm->ba3v;
            #pragma unroll 16
            for (int s = 0; s < TT; s++)
                e += tanha(z1p[s] + zp[s * NIN]) * sm->wa3s[s];
            const float xv = dx[(b * TT + t) * NIN + n];
            const float p = __expf(e);
            float ssum = p;
            #pragma unroll
            for (int off = 16; off; off >>= 1) ssum += __shfl_xor_sync(0xffffffffu, ssum, off);
            if (lane == 0) sm->reds[wid] = ssum;
            __syncthreads();
            const int wb = bh * 4;
            const float tot = sm->reds[wb] + sm->reds[wb + 1] + sm->reds[wb + 2] + sm->reds[wb + 3];
            XtR[(HH + n) * BB + b] = (p / tot) * xv;
        }
        grid_sync();   // wx visible

        // ===== Phase B: smem-staged gates GEMM, output-paired FFMA2 =====
        ull acc[8];     // [batch j (2)][col cl (2)][pair: (i,f) / (g,o)]
        #pragma unroll
        for (int i = 0; i < 8; i++) acc[i] = 0ull;

        // stage chunk 0
        {
            const float* src = XtR;
            for (int i = tid; i < (KCHUNK * BB) / 4; i += NTHREADS)
                cpasync16(xs_base0 + i * 16, src + i * 4);
            asm volatile("cp.async.commit_group;");
        }
        for (int c = 0; c < NCHUNK; c++) {
            if (c + 1 < NCHUNK) {
                const float* src = XtR + (c + 1) * KCHUNK * BB;
                const unsigned dst = ((c + 1) & 1) ? xs_base1 : xs_base0;
                for (int i = tid; i < (KCHUNK * BB) / 4; i += NTHREADS)
                    cpasync16(dst + i * 16, src + i * 4);
                asm volatile("cp.async.commit_group;");
                asm volatile("cp.async.wait_group 1;");
            } else {
                asm volatile("cp.async.wait_group 0;");
            }
            __syncthreads();
            {
                const float* xp = &sm->u.xs[c & 1][b0];
                // 16 floats per k = 4 ulonglong2; base already offset by og*8 floats
                const ulonglong2* wp = (const ulonglong2*)&sm->ws[(c * KCHUNK) * 16 + og * 8];
                #pragma unroll 8
                for (int kl = 0; kl < KCHUNK; kl++) {
                    const float2 xv = *(const float2*)(xp + kl * BB);
                    const ull xd0 = dupf(xv.x);
                    const ull xd1 = dupf(xv.y);
                    const ulonglong2 wA = wp[kl * 4 + 0];   // col cl=0: (wi,wf),(wg,wo)
                    const ulonglong2 wB = wp[kl * 4 + 1];   // col cl=1
                    acc[0] = ffma2(xd0, wA.x, acc[0]);
                    acc[1] = ffma2(xd0, wA.y, acc[1]);
                    acc[2] = ffma2(xd0, wB.x, acc[2]);
                    acc[3] = ffma2(xd0, wB.y, acc[3]);
                    acc[4] = ffma2(xd1, wA.x, acc[4]);
                    acc[5] = ffma2(xd1, wA.y, acc[5]);
                    acc[6] = ffma2(xd1, wB.x, acc[6]);
                    acc[7] = ffma2(xd1, wB.y, acc[7]);
                }
            }
            __syncthreads();
        }

        // pointwise LSTM: 2 batches x 2 cols per thread
        float hvv[2][2], cvv[2][2];
        #pragma unroll
        for (int j = 0; j < 2; j++) {
            #pragma unroll
            for (int cl = 0; cl < 2; cl++) {
                const ull aif = acc[j * 4 + cl * 2 + 0];
                const ull ago = acc[j * 4 + cl * 2 + 1];
                const float gi = f2lo(aif) + biasv[cl * 4 + 0];
                const float gf = f2hi(aif) + biasv[cl * 4 + 1];
                const float gg = f2lo(ago) + biasv[cl * 4 + 2];
                const float go = f2hi(ago) + biasv[cl * 4 + 3];
                const float cn = sigm(gf) * creg[j * 2 + cl] + sigm(gi) * tanha(gg);
                const float hn = sigm(go) * tanha(cn);
                creg[j * 2 + cl] = cn;
                cvv[j][cl] = cn; hvv[j][cl] = hn;
            }
        }
        {
            const int colb = c0 + og * 2;
            #pragma unroll
            for (int cl = 0; cl < 2; cl++)    // [k][b] layout for next GEMM
                *(float2*)&XtW[(colb + cl) * BB + b0] = make_float2(hvv[0][cl], hvv[1][cl]);
            #pragma unroll
            for (int j = 0; j < 2; j++) {     // [b][k] layouts for next phase A
                const int b = b0 + j;
                *(float2*)&g_Hb[b * HH + colb] = make_float2(hvv[j][0], hvv[j][1]);
                *(float2*)&g_Cb[b * HH + colb] = make_float2(cvv[j][0], cvv[j][1]);
                stcs2(&out[(b * TT + t) * HH + colb], hvv[j][0], hvv[j][1]);
            }
        }
        if (t < TT - 1) grid_sync();   // h(t), c(t) visible
    }
}

// ---------------- launch ----------------
extern "C" void kernel_launch(void* const* d_in, const int* in_sizes, int n_in,
                              void* d_out, int out_size)
{
    const float* dx   = (const float*)d_in[0];
    const float* W_a1 = (const float*)d_in[1];
    const float* b_a1 = (const float*)d_in[2];
    const float* W_a2 = (const float*)d_in[3];
    const float* b_a2 = (const float*)d_in[4];
    const float* W_a3 = (const float*)d_in[5];
    const float* b_a3 = (const float*)d_in[6];
    const float* W_ih = (const float*)d_in[7];
    const float* W_hh = (const float*)d_in[8];
    const float* b_ih = (const float*)d_in[9];
    const float* b_hh = (const float*)d_in[10];
    float* out = (float*)d_out;

    const size_t smem = sizeof(SmemMain);
    cudaFuncSetAttribute(attn_lstm_kernel,
                         cudaFuncAttributeMaxDynamicSharedMemorySize, (int)smem);
    attn_lstm_kernel<<<GRID, NTHREADS, smem>>>(dx, W_a1, b_a1, W_a2, b_a2, W_a3,
                                               b_a3, W_ih, W_hh, b_ih, b_hh, out);
}